// round 14
// baseline (speedup 1.0000x reference)
#include <cuda_runtime.h>
#include <math.h>

#define NMAX 100000
#define CAP  40      // max kept (coeff>0) edges per node; lambda~13.3, max~33
#define EPB  256     // edges per block in bucket kernel

__device__ int g_cnt[NMAX];                                   // zero at load; node kernel resets
__device__ __align__(16) float g_payload[(size_t)NMAX * CAP * 16];

// ---------------------------------------------------------------------------
// Bucket phase: R4-style coalesced staging, then 4x STG.128 of the 16-float
// payload into this edge's bucket slot (int atomicAdd allocates the slot).
// ---------------------------------------------------------------------------
__global__ void __launch_bounds__(EPB)
bucket_kernel(const float* __restrict__ edge_sca,
              const float* __restrict__ edge_vec,
              const float* __restrict__ gds,
              const int*   __restrict__ src_idx,
              int E) {
    __shared__ float s_sca[EPB * 6];
    __shared__ float s_vec[EPB * 9];

    int blockStart = blockIdx.x * EPB;
    int tid = threadIdx.x;
    int nEdges = min(EPB, E - blockStart);

    if (nEdges == EPB) {
        const float4* g4s = (const float4*)(edge_sca + (size_t)blockStart * 6);
        float4* s4s = (float4*)s_sca;
#pragma unroll 2
        for (int i = tid; i < (EPB * 6) / 4; i += EPB)
            s4s[i] = g4s[i];
        const float4* g4v = (const float4*)(edge_vec + (size_t)blockStart * 9);
        float4* s4v = (float4*)s_vec;
#pragma unroll 3
        for (int i = tid; i < (EPB * 9) / 4; i += EPB)
            s4v[i] = g4v[i];
    } else {
        for (int i = tid; i < nEdges * 6; i += EPB)
            s_sca[i] = edge_sca[(size_t)blockStart * 6 + i];
        for (int i = tid; i < nEdges * 9; i += EPB)
            s_vec[i] = edge_vec[(size_t)blockStart * 9 + i];
    }
    __syncthreads();

    if (tid >= nEdges) return;
    int e = blockStart + tid;

    float dist = __ldg(gds + e);
    if (dist > 10.0f || dist < 0.0f) return;      // coeff == 0 -> drop
    float coeff = 0.5f * (__cosf(dist * 0.31415926535f) + 1.0f);

    int src = __ldg(src_idx + e);
    int pos = atomicAdd(&g_cnt[src], 1);
    if (pos >= CAP) return;                       // statistically unreachable

    float es[6];
#pragma unroll
    for (int c = 0; c < 6; c++) es[c] = s_sca[tid * 6 + c] * coeff;
    float ev[9];
#pragma unroll
    for (int c = 0; c < 9; c++) ev[c] = s_vec[tid * 9 + c] * coeff;

    float4* dst = (float4*)(g_payload + ((size_t)src * CAP + pos) * 16);
    dst[0] = make_float4(coeff, es[0], es[1], es[2]);
    dst[1] = make_float4(es[3], es[4], es[5], ev[0]);
    dst[2] = make_float4(ev[1], ev[2], ev[3], ev[4]);
    dst[3] = make_float4(ev[5], ev[6], ev[7], ev[8]);
}

// ---------------------------------------------------------------------------
// Node phase: R10 structure + register gather of the bucketed payload.
// 2 nodes/thread, 4 lanes/node; lane j reads quarter j of each edge's 64B.
// ---------------------------------------------------------------------------
#define O_NSS   0      // 4x16
#define O_BNSS  64     // 16
#define O_ESS   80     // 6x16
#define O_BESS  176    // 16
#define O_NSV   192    // 4x16
#define O_BNSV  256    // 16
#define O_ESV   272    // 6x16
#define O_BESV  368    // 16
#define O_NVV   384    // 3x16
#define O_EVV   432    // 3x16
#define O_LV    480    // 16x16
#define O_LV2   736    // 16x16
#define O_LS    992    // 32x16
#define O_GATE  1504   // 16x16
#define O_BGATE 1760   // 16
#define O_DIR   1776   // 16x16
#define SW_TOT  2032

#define NPB 64         // nodes per block
#define TPB 128        // threads (4 lanes x 32 node-pairs)
#define HALF_ND 32
#define BUF_W 68       // 64 payload + 4 pad floats

__global__ void __launch_bounds__(TPB)
node_kernel(const float* __restrict__ node_sca,
            const float* __restrict__ node_vec,
            const float* __restrict__ W_nss, const float* __restrict__ b_nss,
            const float* __restrict__ W_ess, const float* __restrict__ b_ess,
            const float* __restrict__ W_nsv, const float* __restrict__ b_nsv,
            const float* __restrict__ W_esv, const float* __restrict__ b_esv,
            const float* __restrict__ W_nvv, const float* __restrict__ W_evv,
            const float* __restrict__ W_lv,  const float* __restrict__ W_lv2,
            const float* __restrict__ W_ls,  const float* __restrict__ W_gate,
            const float* __restrict__ b_gate,const float* __restrict__ W_dir,
            float* __restrict__ out, int N) {
    __shared__ __align__(16) float sW[SW_TOT];
    __shared__ float s_nv[NPB * 9];
    __shared__ __align__(16) float bufA[NPB][BUF_W];  // aggr -> osca -> ovec
    __shared__ __align__(16) float bufB[NPB][BUF_W];  // v_inter + v_norm

    int tid = threadIdx.x;
    int ndA = tid >> 2;          // 0..31
    int ndB = ndA + HALF_ND;     // 32..63
    int j   = tid & 3;
    int o0  = j * 4;
    int lane = tid & 31;
    int qbase = lane & ~3;       // first lane of this quad
    int blockStart = blockIdx.x * NPB;
    int nNodes = min(NPB, N - blockStart);
    int nA = blockStart + ndA;
    int nB = blockStart + ndB;
    bool actA = (ndA < nNodes);
    bool actB = (ndB < nNodes);

    {   // weights -> shared
        const float* srcs[16] = {W_nss, b_nss, W_ess, b_ess, W_nsv, b_nsv,
                                 W_esv, b_esv, W_nvv, W_evv, W_lv, W_lv2,
                                 W_ls, W_gate, b_gate, W_dir};
        const int offs[17] = {O_NSS, O_BNSS, O_ESS, O_BESS, O_NSV, O_BNSV,
                              O_ESV, O_BESV, O_NVV, O_EVV, O_LV, O_LV2,
                              O_LS, O_GATE, O_BGATE, O_DIR, SW_TOT};
        for (int a = 0; a < 16; a++) {
            int cnt = offs[a + 1] - offs[a];
            for (int i = tid; i < cnt; i += TPB)
                sW[offs[a] + i] = srcs[a][i];
        }
    }
    {   // node_vec -> shared (coalesced)
        for (int i = tid; i < nNodes * 9; i += TPB)
            s_nv[i] = node_vec[(size_t)blockStart * 9 + i];
    }
    __syncthreads();

    // ---- Phase 1 per node: gather bucketed payload + projections ----
#pragma unroll
    for (int half = 0; half < 2; half++) {
        int nd = half ? ndB : ndA;
        int n  = half ? nB  : nA;
        bool act = half ? actB : actA;
        if (!act) continue;

        // gather: lane j accumulates its 4-float quarter across the edge list
        int cnt = min(g_cnt[n], CAP);
        float a0 = 0.f, a1 = 0.f, a2 = 0.f, a3 = 0.f;
        const float4* base =
            (const float4*)(g_payload + (size_t)n * CAP * 16) + j;
#pragma unroll 2
        for (int i = 0; i < cnt; i++) {
            float4 v = base[i * 4];
            a0 += v.x; a1 += v.y; a2 += v.z; a3 += v.w;
        }
        if (j == 0) g_cnt[n] = 0;     // reset for next graph replay

        // distribute quarters across the quad -> full 16-float statistic
        float accv[16];
#pragma unroll
        for (int q = 0; q < 4; q++) {
            accv[q * 4 + 0] = __shfl_sync(0xffffffffu, a0, qbase + q);
            accv[q * 4 + 1] = __shfl_sync(0xffffffffu, a1, qbase + q);
            accv[q * 4 + 2] = __shfl_sync(0xffffffffu, a2, qbase + q);
            accv[q * 4 + 3] = __shfl_sync(0xffffffffu, a3, qbase + q);
        }

        float4 ns4 = ((const float4*)node_sca)[n];
        float ns[4] = {ns4.x, ns4.y, ns4.z, ns4.w};
        float nv[9];
#pragma unroll
        for (int i = 0; i < 9; i++) nv[i] = s_nv[nd * 9 + i];

        float Cs = accv[0];
        float* Es = accv + 1;
        float* Ev = accv + 7;

#pragma unroll
        for (int cc = 0; cc < 4; cc++) {
            int c = o0 + cc;
            float nss = sW[O_BNSS + c];
            float nsv = sW[O_BNSV + c];
#pragma unroll
            for (int k = 0; k < 4; k++) {
                nss += ns[k] * sW[O_NSS + k * 16 + c];
                nsv += ns[k] * sW[O_NSV + k * 16 + c];
            }
            float ess = sW[O_BESS + c] * Cs;
            float esv = sW[O_BESV + c] * Cs;
#pragma unroll
            for (int k = 0; k < 6; k++) {
                ess += Es[k] * sW[O_ESS + k * 16 + c];
                esv += Es[k] * sW[O_ESV + k * 16 + c];
            }
            float av[3];
#pragma unroll
            for (int i = 0; i < 3; i++) {
                float nvv = 0.f, evv = 0.f;
#pragma unroll
                for (int k = 0; k < 3; k++) {
                    nvv += nv[k * 3 + i] * sW[O_NVV + k * 16 + c];
                    evv += Ev[k * 3 + i] * sW[O_EVV + k * 16 + c];
                }
                av[i] = nvv * esv + nsv * evv;
            }
            *(float4*)&bufA[nd][c * 4] = make_float4(av[0], av[1], av[2], nss * ess);
        }
    }
    __syncwarp();

    // ---- Phase 2: lv + ls-scalar-half, both nodes share weight loads ----
    float viA[4][3], viB[4][3], oscaA[4], oscaB[4];
#pragma unroll
    for (int oo = 0; oo < 4; oo++) {
        viA[oo][0] = viA[oo][1] = viA[oo][2] = 0.f;
        viB[oo][0] = viB[oo][1] = viB[oo][2] = 0.f;
        oscaA[oo] = oscaB[oo] = 0.f;
    }
#pragma unroll
    for (int c = 0; c < 16; c++) {
        float4 wlv = *(const float4*)&sW[O_LV + c * 16 + o0];
        float4 wls = *(const float4*)&sW[O_LS + (c + 16) * 16 + o0];
        float4 a = *(const float4*)&bufA[ndA][c * 4];
        float4 b = *(const float4*)&bufA[ndB][c * 4];
        viA[0][0] += a.x * wlv.x; viA[0][1] += a.y * wlv.x; viA[0][2] += a.z * wlv.x;
        viA[1][0] += a.x * wlv.y; viA[1][1] += a.y * wlv.y; viA[1][2] += a.z * wlv.y;
        viA[2][0] += a.x * wlv.z; viA[2][1] += a.y * wlv.z; viA[2][2] += a.z * wlv.z;
        viA[3][0] += a.x * wlv.w; viA[3][1] += a.y * wlv.w; viA[3][2] += a.z * wlv.w;
        oscaA[0] += a.w * wls.x; oscaA[1] += a.w * wls.y;
        oscaA[2] += a.w * wls.z; oscaA[3] += a.w * wls.w;
        viB[0][0] += b.x * wlv.x; viB[0][1] += b.y * wlv.x; viB[0][2] += b.z * wlv.x;
        viB[1][0] += b.x * wlv.y; viB[1][1] += b.y * wlv.y; viB[1][2] += b.z * wlv.y;
        viB[2][0] += b.x * wlv.z; viB[2][1] += b.y * wlv.z; viB[2][2] += b.z * wlv.z;
        viB[3][0] += b.x * wlv.w; viB[3][1] += b.y * wlv.w; viB[3][2] += b.z * wlv.w;
        oscaB[0] += b.w * wls.x; oscaB[1] += b.w * wls.y;
        oscaB[2] += b.w * wls.z; oscaB[3] += b.w * wls.w;
    }
#pragma unroll
    for (int oo = 0; oo < 4; oo++) {
        float vnA = sqrtf(viA[oo][0] * viA[oo][0] + viA[oo][1] * viA[oo][1] +
                          viA[oo][2] * viA[oo][2]);
        *(float4*)&bufB[ndA][(o0 + oo) * 4] =
            make_float4(viA[oo][0], viA[oo][1], viA[oo][2], vnA);
        float vnB = sqrtf(viB[oo][0] * viB[oo][0] + viB[oo][1] * viB[oo][1] +
                          viB[oo][2] * viB[oo][2]);
        *(float4*)&bufB[ndB][(o0 + oo) * 4] =
            make_float4(viB[oo][0], viB[oo][1], viB[oo][2], vnB);
    }
    __syncwarp();

    // ---- Phase 3: osca v_norm-half; publish osca ----
#pragma unroll
    for (int c = 0; c < 16; c++) {
        float4 wls = *(const float4*)&sW[O_LS + c * 16 + o0];
        float vnA = bufB[ndA][c * 4 + 3];
        float vnB = bufB[ndB][c * 4 + 3];
        oscaA[0] += vnA * wls.x; oscaA[1] += vnA * wls.y;
        oscaA[2] += vnA * wls.z; oscaA[3] += vnA * wls.w;
        oscaB[0] += vnB * wls.x; oscaB[1] += vnB * wls.y;
        oscaB[2] += vnB * wls.z; oscaB[3] += vnB * wls.w;
    }
    *(float4*)&bufA[ndA][o0] = make_float4(oscaA[0], oscaA[1], oscaA[2], oscaA[3]);
    *(float4*)&bufA[ndB][o0] = make_float4(oscaB[0], oscaB[1], oscaB[2], oscaB[3]);
    __syncwarp();

    // ---- Phase 4: gate ----
    float gateA[4], gateB[4];
#pragma unroll
    for (int oo = 0; oo < 4; oo++) gateA[oo] = gateB[oo] = sW[O_BGATE + o0 + oo];
#pragma unroll
    for (int c4 = 0; c4 < 4; c4++) {
        float4 ocA = *(const float4*)&bufA[ndA][c4 * 4];
        float4 ocB = *(const float4*)&bufA[ndB][c4 * 4];
        float av[4] = {ocA.x, ocA.y, ocA.z, ocA.w};
        float bv[4] = {ocB.x, ocB.y, ocB.z, ocB.w};
#pragma unroll
        for (int q = 0; q < 4; q++) {
            float4 wg = *(const float4*)&sW[O_GATE + (c4 * 4 + q) * 16 + o0];
            gateA[0] += av[q] * wg.x; gateA[1] += av[q] * wg.y;
            gateA[2] += av[q] * wg.z; gateA[3] += av[q] * wg.w;
            gateB[0] += bv[q] * wg.x; gateB[1] += bv[q] * wg.y;
            gateB[2] += bv[q] * wg.z; gateB[3] += bv[q] * wg.w;
        }
    }
#pragma unroll
    for (int oo = 0; oo < 4; oo++) {
        gateA[oo] = 1.0f / (1.0f + __expf(-gateA[oo]));
        gateB[oo] = 1.0f / (1.0f + __expf(-gateB[oo]));
    }
    __syncwarp();   // osca reads done; bufA reusable for ovec

    // ---- Phase 5: lv2 -> ovec (gated); publish ----
    float ovA[4][3], ovB[4][3];
#pragma unroll
    for (int oo = 0; oo < 4; oo++) {
        ovA[oo][0] = ovA[oo][1] = ovA[oo][2] = 0.f;
        ovB[oo][0] = ovB[oo][1] = ovB[oo][2] = 0.f;
    }
#pragma unroll
    for (int c = 0; c < 16; c++) {
        float4 w = *(const float4*)&sW[O_LV2 + c * 16 + o0];
        float4 vA = *(const float4*)&bufB[ndA][c * 4];
        float4 vB = *(const float4*)&bufB[ndB][c * 4];
        ovA[0][0] += vA.x * w.x; ovA[0][1] += vA.y * w.x; ovA[0][2] += vA.z * w.x;
        ovA[1][0] += vA.x * w.y; ovA[1][1] += vA.y * w.y; ovA[1][2] += vA.z * w.y;
        ovA[2][0] += vA.x * w.z; ovA[2][1] += vA.y * w.z; ovA[2][2] += vA.z * w.z;
        ovA[3][0] += vA.x * w.w; ovA[3][1] += vA.y * w.w; ovA[3][2] += vA.z * w.w;
        ovB[0][0] += vB.x * w.x; ovB[0][1] += vB.y * w.x; ovB[0][2] += vB.z * w.x;
        ovB[1][0] += vB.x * w.y; ovB[1][1] += vB.y * w.y; ovB[1][2] += vB.z * w.y;
        ovB[2][0] += vB.x * w.z; ovB[2][1] += vB.y * w.z; ovB[2][2] += vB.z * w.z;
        ovB[3][0] += vB.x * w.w; ovB[3][1] += vB.y * w.w; ovB[3][2] += vB.z * w.w;
    }
#pragma unroll
    for (int oo = 0; oo < 4; oo++) {
        ovA[oo][0] *= gateA[oo]; ovA[oo][1] *= gateA[oo]; ovA[oo][2] *= gateA[oo];
        ovB[oo][0] *= gateB[oo]; ovB[oo][1] *= gateB[oo]; ovB[oo][2] *= gateB[oo];
        *(float4*)&bufA[ndA][(o0 + oo) * 4] =
            make_float4(ovA[oo][0], ovA[oo][1], ovA[oo][2], 0.f);
        *(float4*)&bufA[ndB][(o0 + oo) * 4] =
            make_float4(ovB[oo][0], ovB[oo][1], ovB[oo][2], 0.f);
    }
    __syncwarp();

    // ---- Phase 6: direction + VNLeakyReLU + writes ----
    float dA[4][3], dB[4][3];
#pragma unroll
    for (int oo = 0; oo < 4; oo++) {
        dA[oo][0] = dA[oo][1] = dA[oo][2] = 0.f;
        dB[oo][0] = dB[oo][1] = dB[oo][2] = 0.f;
    }
#pragma unroll
    for (int c = 0; c < 16; c++) {
        float4 w = *(const float4*)&sW[O_DIR + c * 16 + o0];
        float4 vA = *(const float4*)&bufA[ndA][c * 4];
        float4 vB = *(const float4*)&bufA[ndB][c * 4];
        dA[0][0] += vA.x * w.x; dA[0][1] += vA.y * w.x; dA[0][2] += vA.z * w.x;
        dA[1][0] += vA.x * w.y; dA[1][1] += vA.y * w.y; dA[1][2] += vA.z * w.y;
        dA[2][0] += vA.x * w.z; dA[2][1] += vA.y * w.z; dA[2][2] += vA.z * w.z;
        dA[3][0] += vA.x * w.w; dA[3][1] += vA.y * w.w; dA[3][2] += vA.z * w.w;
        dB[0][0] += vB.x * w.x; dB[0][1] += vB.y * w.x; dB[0][2] += vB.z * w.x;
        dB[1][0] += vB.x * w.y; dB[1][1] += vB.y * w.y; dB[1][2] += vB.z * w.y;
        dB[2][0] += vB.x * w.z; dB[2][1] += vB.y * w.z; dB[2][2] += vB.z * w.z;
        dB[3][0] += vB.x * w.w; dB[3][1] += vB.y * w.w; dB[3][2] += vB.z * w.w;
    }

    float* out_vec = out + (size_t)N * 16;
#pragma unroll
    for (int half = 0; half < 2; half++) {
        bool act = half ? actB : actA;
        if (!act) continue;
        int n = half ? nB : nA;
        float (*ov)[3] = half ? ovB : ovA;
        float (*d)[3]  = half ? dB  : dA;
        float* osca    = half ? oscaB : oscaA;

        float res[12];
#pragma unroll
        for (int oo = 0; oo < 4; oo++) {
            float v0 = ov[oo][0], v1 = ov[oo][1], v2 = ov[oo][2];
            float d0 = d[oo][0], d1 = d[oo][1], d2 = d[oo][2];
            float dot = v0 * d0 + v1 * d1 + v2 * d2;
            float r0 = v0, r1 = v1, r2 = v2;
            if (dot < 0.0f) {
                float k = 0.8f * dot / (d0 * d0 + d1 * d1 + d2 * d2 + 1e-6f);
                r0 = v0 - k * d0; r1 = v1 - k * d1; r2 = v2 - k * d2;
            }
            res[oo * 3 + 0] = r0; res[oo * 3 + 1] = r1; res[oo * 3 + 2] = r2;
        }
        float4* dv = (float4*)(out_vec + (size_t)n * 48 + j * 12);
#pragma unroll
        for (int q = 0; q < 3; q++)
            dv[q] = make_float4(res[q * 4 + 0], res[q * 4 + 1],
                                res[q * 4 + 2], res[q * 4 + 3]);

        float s0 = osca[0], s1 = osca[1], s2 = osca[2], s3 = osca[3];
        s0 = (s0 >= 0.f) ? s0 : 0.01f * s0;
        s1 = (s1 >= 0.f) ? s1 : 0.01f * s1;
        s2 = (s2 >= 0.f) ? s2 : 0.01f * s2;
        s3 = (s3 >= 0.f) ? s3 : 0.01f * s3;
        ((float4*)(out + (size_t)n * 16 + o0))[0] = make_float4(s0, s1, s2, s3);
    }
}

// ---------------------------------------------------------------------------
extern "C" void kernel_launch(void* const* d_in, const int* in_sizes, int n_in,
                              void* d_out, int out_size) {
    const float* node_sca = (const float*)d_in[0];
    const float* node_vec = (const float*)d_in[1];
    const float* edge_sca = (const float*)d_in[2];
    const float* edge_vec = (const float*)d_in[3];
    const float* gds      = (const float*)d_in[4];
    const int*   ei       = (const int*)d_in[5];   // [2,E]; row 0 = src
    const float* W_nss  = (const float*)d_in[6];
    const float* b_nss  = (const float*)d_in[7];
    const float* W_ess  = (const float*)d_in[8];
    const float* b_ess  = (const float*)d_in[9];
    const float* W_nsv  = (const float*)d_in[10];
    const float* b_nsv  = (const float*)d_in[11];
    const float* W_esv  = (const float*)d_in[12];
    const float* b_esv  = (const float*)d_in[13];
    const float* W_nvv  = (const float*)d_in[14];
    const float* W_evv  = (const float*)d_in[15];
    const float* W_lv   = (const float*)d_in[16];
    const float* W_lv2  = (const float*)d_in[17];
    const float* W_ls   = (const float*)d_in[18];
    const float* W_gate = (const float*)d_in[19];
    const float* b_gate = (const float*)d_in[20];
    const float* W_dir  = (const float*)d_in[21];

    int N = in_sizes[0] / 4;
    int E = in_sizes[4];

    int eblocks = (E + EPB - 1) / EPB;
    bucket_kernel<<<eblocks, EPB>>>(edge_sca, edge_vec, gds, ei, E);

    int nblocks = (N + NPB - 1) / NPB;
    node_kernel<<<nblocks, TPB>>>(node_sca, node_vec,
                                  W_nss, b_nss, W_ess, b_ess,
                                  W_nsv, b_nsv, W_esv, b_esv,
                                  W_nvv, W_evv, W_lv, W_lv2,
                                  W_ls, W_gate, b_gate, W_dir,
                                  (float*)d_out, N);
}

// round 15
// speedup vs baseline: 1.5231x; 1.5231x over previous
#include <cuda_runtime.h>
#include <math.h>

#define NMAX 100000
#define ACC_W 16   // [coeff, edge_sca*coeff (6), edge_vec*coeff (9)]
#define EPB 256    // edges per block in edge kernel

__device__ __align__(16) float g_acc[NMAX * ACC_W];   // zero-initialized at load

// ---------------------------------------------------------------------------
// Edge phase: staged coalesced loads + red.v4; gds/src loads issued BEFORE
// the staging barrier so their DRAM latency overlaps the staging loop.
// ---------------------------------------------------------------------------
__device__ __forceinline__ void red_v4(float* p, float a, float b, float c, float d) {
    asm volatile("red.global.add.v4.f32 [%0], {%1,%2,%3,%4};"
                 :: "l"(p), "f"(a), "f"(b), "f"(c), "f"(d) : "memory");
}

__global__ void __launch_bounds__(EPB)
edge_kernel(const float* __restrict__ edge_sca,
            const float* __restrict__ edge_vec,
            const float* __restrict__ gds,
            const int*   __restrict__ src_idx,
            int E) {
    __shared__ float s_sca[EPB * 6];
    __shared__ float s_vec[EPB * 9];

    int blockStart = blockIdx.x * EPB;
    int tid = threadIdx.x;
    int nEdges = min(EPB, E - blockStart);
    int e = blockStart + tid;

    // early loads: overlap with staging below
    float dist = 1e30f;
    int src = 0;
    if (tid < nEdges) {
        dist = __ldg(gds + e);
        src  = __ldg(src_idx + e);
    }

    if (nEdges == EPB) {
        const float4* g4s = (const float4*)(edge_sca + (size_t)blockStart * 6);
        float4* s4s = (float4*)s_sca;
#pragma unroll 2
        for (int i = tid; i < (EPB * 6) / 4; i += EPB)
            s4s[i] = g4s[i];
        const float4* g4v = (const float4*)(edge_vec + (size_t)blockStart * 9);
        float4* s4v = (float4*)s_vec;
#pragma unroll 3
        for (int i = tid; i < (EPB * 9) / 4; i += EPB)
            s4v[i] = g4v[i];
    } else {
        for (int i = tid; i < nEdges * 6; i += EPB)
            s_sca[i] = edge_sca[(size_t)blockStart * 6 + i];
        for (int i = tid; i < nEdges * 9; i += EPB)
            s_vec[i] = edge_vec[(size_t)blockStart * 9 + i];
    }
    __syncthreads();

    if (tid >= nEdges) return;
    if (dist > 10.0f || dist < 0.0f) return;     // coeff == 0 -> no contribution
    float coeff = 0.5f * (__cosf(dist * 0.31415926535f) + 1.0f);

    float es[6];
#pragma unroll
    for (int c = 0; c < 6; c++) es[c] = s_sca[tid * 6 + c] * coeff;
    float ev[9];
#pragma unroll
    for (int c = 0; c < 9; c++) ev[c] = s_vec[tid * 9 + c] * coeff;

    float* base = g_acc + (size_t)src * ACC_W;
    red_v4(base + 0,  coeff, es[0], es[1], es[2]);
    red_v4(base + 4,  es[3], es[4], es[5], ev[0]);
    red_v4(base + 8,  ev[1], ev[2], ev[3], ev[4]);
    red_v4(base + 12, ev[5], ev[6], ev[7], ev[8]);
}

// ---------------------------------------------------------------------------
// Node phase: R10 structure (best known). 2 nodes/thread, 4 lanes/node,
// 128-bit smem traffic. Re-zeroes g_acc after consuming (replay invariant).
// ---------------------------------------------------------------------------
#define O_NSS   0      // 4x16
#define O_BNSS  64     // 16
#define O_ESS   80     // 6x16
#define O_BESS  176    // 16
#define O_NSV   192    // 4x16
#define O_BNSV  256    // 16
#define O_ESV   272    // 6x16
#define O_BESV  368    // 16
#define O_NVV   384    // 3x16
#define O_EVV   432    // 3x16
#define O_LV    480    // 16x16
#define O_LV2   736    // 16x16
#define O_LS    992    // 32x16
#define O_GATE  1504   // 16x16
#define O_BGATE 1760   // 16
#define O_DIR   1776   // 16x16
#define SW_TOT  2032

#define NPB 64         // nodes per block
#define TPB 128        // threads (4 lanes x 32 node-pairs)
#define HALF_ND 32
#define BUF_W 68       // 64 payload + 4 pad floats

__global__ void __launch_bounds__(TPB)
node_kernel(const float* __restrict__ node_sca,
            const float* __restrict__ node_vec,
            const float* __restrict__ W_nss, const float* __restrict__ b_nss,
            const float* __restrict__ W_ess, const float* __restrict__ b_ess,
            const float* __restrict__ W_nsv, const float* __restrict__ b_nsv,
            const float* __restrict__ W_esv, const float* __restrict__ b_esv,
            const float* __restrict__ W_nvv, const float* __restrict__ W_evv,
            const float* __restrict__ W_lv,  const float* __restrict__ W_lv2,
            const float* __restrict__ W_ls,  const float* __restrict__ W_gate,
            const float* __restrict__ b_gate,const float* __restrict__ W_dir,
            float* __restrict__ out, int N) {
    __shared__ __align__(16) float sW[SW_TOT];
    __shared__ float s_nv[NPB * 9];
    __shared__ __align__(16) float bufA[NPB][BUF_W];  // aggr -> osca -> ovec
    __shared__ __align__(16) float bufB[NPB][BUF_W];  // v_inter + v_norm

    int tid = threadIdx.x;
    int ndA = tid >> 2;          // 0..31
    int ndB = ndA + HALF_ND;     // 32..63
    int j   = tid & 3;
    int o0  = j * 4;
    int blockStart = blockIdx.x * NPB;
    int nNodes = min(NPB, N - blockStart);
    int nA = blockStart + ndA;
    int nB = blockStart + ndB;
    bool actA = (ndA < nNodes);
    bool actB = (ndB < nNodes);

    {   // weights -> shared
        const float* srcs[16] = {W_nss, b_nss, W_ess, b_ess, W_nsv, b_nsv,
                                 W_esv, b_esv, W_nvv, W_evv, W_lv, W_lv2,
                                 W_ls, W_gate, b_gate, W_dir};
        const int offs[17] = {O_NSS, O_BNSS, O_ESS, O_BESS, O_NSV, O_BNSV,
                              O_ESV, O_BESV, O_NVV, O_EVV, O_LV, O_LV2,
                              O_LS, O_GATE, O_BGATE, O_DIR, SW_TOT};
        for (int a = 0; a < 16; a++) {
            int cnt = offs[a + 1] - offs[a];
            for (int i = tid; i < cnt; i += TPB)
                sW[offs[a] + i] = srcs[a][i];
        }
    }
    {   // node_vec -> shared (coalesced)
        for (int i = tid; i < nNodes * 9; i += TPB)
            s_nv[i] = node_vec[(size_t)blockStart * 9 + i];
    }
    __syncthreads();

    // ---- Phase 1 per node (inputs transient) ----
#pragma unroll
    for (int half = 0; half < 2; half++) {
        int nd = half ? ndB : ndA;
        int n  = half ? nB  : nA;
        bool act = half ? actB : actA;
        if (!act) continue;

        float4 ns4 = ((const float4*)node_sca)[n];
        float ns[4] = {ns4.x, ns4.y, ns4.z, ns4.w};
        float nv[9];
#pragma unroll
        for (int i = 0; i < 9; i++) nv[i] = s_nv[nd * 9 + i];
        float accv[16];
        {
            float4* a4 = (float4*)(g_acc + (size_t)n * ACC_W);
#pragma unroll
            for (int q = 0; q < 4; q++) {
                float4 v = a4[q];
                accv[q * 4 + 0] = v.x; accv[q * 4 + 1] = v.y;
                accv[q * 4 + 2] = v.z; accv[q * 4 + 3] = v.w;
            }
            a4[j] = make_float4(0.f, 0.f, 0.f, 0.f);   // reset quarter j
        }
        float Cs = accv[0];
        float* Es = accv + 1;
        float* Ev = accv + 7;

#pragma unroll
        for (int cc = 0; cc < 4; cc++) {
            int c = o0 + cc;
            float nss = sW[O_BNSS + c];
            float nsv = sW[O_BNSV + c];
#pragma unroll
            for (int k = 0; k < 4; k++) {
                nss += ns[k] * sW[O_NSS + k * 16 + c];
                nsv += ns[k] * sW[O_NSV + k * 16 + c];
            }
            float ess = sW[O_BESS + c] * Cs;
            float esv = sW[O_BESV + c] * Cs;
#pragma unroll
            for (int k = 0; k < 6; k++) {
                ess += Es[k] * sW[O_ESS + k * 16 + c];
                esv += Es[k] * sW[O_ESV + k * 16 + c];
            }
            float av[3];
#pragma unroll
            for (int i = 0; i < 3; i++) {
                float nvv = 0.f, evv = 0.f;
#pragma unroll
                for (int k = 0; k < 3; k++) {
                    nvv += nv[k * 3 + i] * sW[O_NVV + k * 16 + c];
                    evv += Ev[k * 3 + i] * sW[O_EVV + k * 16 + c];
                }
                av[i] = nvv * esv + nsv * evv;
            }
            *(float4*)&bufA[nd][c * 4] = make_float4(av[0], av[1], av[2], nss * ess);
        }
    }
    __syncwarp();

    // ---- Phase 2: lv + ls-scalar-half, both nodes share weight loads ----
    float viA[4][3], viB[4][3], oscaA[4], oscaB[4];
#pragma unroll
    for (int oo = 0; oo < 4; oo++) {
        viA[oo][0] = viA[oo][1] = viA[oo][2] = 0.f;
        viB[oo][0] = viB[oo][1] = viB[oo][2] = 0.f;
        oscaA[oo] = oscaB[oo] = 0.f;
    }
#pragma unroll
    for (int c = 0; c < 16; c++) {
        float4 wlv = *(const float4*)&sW[O_LV + c * 16 + o0];
        float4 wls = *(const float4*)&sW[O_LS + (c + 16) * 16 + o0];
        float4 a = *(const float4*)&bufA[ndA][c * 4];
        float4 b = *(const float4*)&bufA[ndB][c * 4];
        viA[0][0] += a.x * wlv.x; viA[0][1] += a.y * wlv.x; viA[0][2] += a.z * wlv.x;
        viA[1][0] += a.x * wlv.y; viA[1][1] += a.y * wlv.y; viA[1][2] += a.z * wlv.y;
        viA[2][0] += a.x * wlv.z; viA[2][1] += a.y * wlv.z; viA[2][2] += a.z * wlv.z;
        viA[3][0] += a.x * wlv.w; viA[3][1] += a.y * wlv.w; viA[3][2] += a.z * wlv.w;
        oscaA[0] += a.w * wls.x; oscaA[1] += a.w * wls.y;
        oscaA[2] += a.w * wls.z; oscaA[3] += a.w * wls.w;
        viB[0][0] += b.x * wlv.x; viB[0][1] += b.y * wlv.x; viB[0][2] += b.z * wlv.x;
        viB[1][0] += b.x * wlv.y; viB[1][1] += b.y * wlv.y; viB[1][2] += b.z * wlv.y;
        viB[2][0] += b.x * wlv.z; viB[2][1] += b.y * wlv.z; viB[2][2] += b.z * wlv.z;
        viB[3][0] += b.x * wlv.w; viB[3][1] += b.y * wlv.w; viB[3][2] += b.z * wlv.w;
        oscaB[0] += b.w * wls.x; oscaB[1] += b.w * wls.y;
        oscaB[2] += b.w * wls.z; oscaB[3] += b.w * wls.w;
    }
#pragma unroll
    for (int oo = 0; oo < 4; oo++) {
        float vnA = sqrtf(viA[oo][0] * viA[oo][0] + viA[oo][1] * viA[oo][1] +
                          viA[oo][2] * viA[oo][2]);
        *(float4*)&bufB[ndA][(o0 + oo) * 4] =
            make_float4(viA[oo][0], viA[oo][1], viA[oo][2], vnA);
        float vnB = sqrtf(viB[oo][0] * viB[oo][0] + viB[oo][1] * viB[oo][1] +
                          viB[oo][2] * viB[oo][2]);
        *(float4*)&bufB[ndB][(o0 + oo) * 4] =
            make_float4(viB[oo][0], viB[oo][1], viB[oo][2], vnB);
    }
    __syncwarp();

    // ---- Phase 3: osca v_norm-half; publish osca ----
#pragma unroll
    for (int c = 0; c < 16; c++) {
        float4 wls = *(const float4*)&sW[O_LS + c * 16 + o0];
        float vnA = bufB[ndA][c * 4 + 3];
        float vnB = bufB[ndB][c * 4 + 3];
        oscaA[0] += vnA * wls.x; oscaA[1] += vnA * wls.y;
        oscaA[2] += vnA * wls.z; oscaA[3] += vnA * wls.w;
        oscaB[0] += vnB * wls.x; oscaB[1] += vnB * wls.y;
        oscaB[2] += vnB * wls.z; oscaB[3] += vnB * wls.w;
    }
    *(float4*)&bufA[ndA][o0] = make_float4(oscaA[0], oscaA[1], oscaA[2], oscaA[3]);
    *(float4*)&bufA[ndB][o0] = make_float4(oscaB[0], oscaB[1], oscaB[2], oscaB[3]);
    __syncwarp();

    // ---- Phase 4: gate ----
    float gateA[4], gateB[4];
#pragma unroll
    for (int oo = 0; oo < 4; oo++) gateA[oo] = gateB[oo] = sW[O_BGATE + o0 + oo];
#pragma unroll
    for (int c4 = 0; c4 < 4; c4++) {
        float4 ocA = *(const float4*)&bufA[ndA][c4 * 4];
        float4 ocB = *(const float4*)&bufA[ndB][c4 * 4];
        float av[4] = {ocA.x, ocA.y, ocA.z, ocA.w};
        float bv[4] = {ocB.x, ocB.y, ocB.z, ocB.w};
#pragma unroll
        for (int q = 0; q < 4; q++) {
            float4 wg = *(const float4*)&sW[O_GATE + (c4 * 4 + q) * 16 + o0];
            gateA[0] += av[q] * wg.x; gateA[1] += av[q] * wg.y;
            gateA[2] += av[q] * wg.z; gateA[3] += av[q] * wg.w;
            gateB[0] += bv[q] * wg.x; gateB[1] += bv[q] * wg.y;
            gateB[2] += bv[q] * wg.z; gateB[3] += bv[q] * wg.w;
        }
    }
#pragma unroll
    for (int oo = 0; oo < 4; oo++) {
        gateA[oo] = 1.0f / (1.0f + __expf(-gateA[oo]));
        gateB[oo] = 1.0f / (1.0f + __expf(-gateB[oo]));
    }
    __syncwarp();   // osca reads done; bufA reusable for ovec

    // ---- Phase 5: lv2 -> ovec (gated); publish ----
    float ovA[4][3], ovB[4][3];
#pragma unroll
    for (int oo = 0; oo < 4; oo++) {
        ovA[oo][0] = ovA[oo][1] = ovA[oo][2] = 0.f;
        ovB[oo][0] = ovB[oo][1] = ovB[oo][2] = 0.f;
    }
#pragma unroll
    for (int c = 0; c < 16; c++) {
        float4 w = *(const float4*)&sW[O_LV2 + c * 16 + o0];
        float4 vA = *(const float4*)&bufB[ndA][c * 4];
        float4 vB = *(const float4*)&bufB[ndB][c * 4];
        ovA[0][0] += vA.x * w.x; ovA[0][1] += vA.y * w.x; ovA[0][2] += vA.z * w.x;
        ovA[1][0] += vA.x * w.y; ovA[1][1] += vA.y * w.y; ovA[1][2] += vA.z * w.y;
        ovA[2][0] += vA.x * w.z; ovA[2][1] += vA.y * w.z; ovA[2][2] += vA.z * w.z;
        ovA[3][0] += vA.x * w.w; ovA[3][1] += vA.y * w.w; ovA[3][2] += vA.z * w.w;
        ovB[0][0] += vB.x * w.x; ovB[0][1] += vB.y * w.x; ovB[0][2] += vB.z * w.x;
        ovB[1][0] += vB.x * w.y; ovB[1][1] += vB.y * w.y; ovB[1][2] += vB.z * w.y;
        ovB[2][0] += vB.x * w.z; ovB[2][1] += vB.y * w.z; ovB[2][2] += vB.z * w.z;
        ovB[3][0] += vB.x * w.w; ovB[3][1] += vB.y * w.w; ovB[3][2] += vB.z * w.w;
    }
#pragma unroll
    for (int oo = 0; oo < 4; oo++) {
        ovA[oo][0] *= gateA[oo]; ovA[oo][1] *= gateA[oo]; ovA[oo][2] *= gateA[oo];
        ovB[oo][0] *= gateB[oo]; ovB[oo][1] *= gateB[oo]; ovB[oo][2] *= gateB[oo];
        *(float4*)&bufA[ndA][(o0 + oo) * 4] =
            make_float4(ovA[oo][0], ovA[oo][1], ovA[oo][2], 0.f);
        *(float4*)&bufA[ndB][(o0 + oo) * 4] =
            make_float4(ovB[oo][0], ovB[oo][1], ovB[oo][2], 0.f);
    }
    __syncwarp();

    // ---- Phase 6: direction + VNLeakyReLU + writes ----
    float dA[4][3], dB[4][3];
#pragma unroll
    for (int oo = 0; oo < 4; oo++) {
        dA[oo][0] = dA[oo][1] = dA[oo][2] = 0.f;
        dB[oo][0] = dB[oo][1] = dB[oo][2] = 0.f;
    }
#pragma unroll
    for (int c = 0; c < 16; c++) {
        float4 w = *(const float4*)&sW[O_DIR + c * 16 + o0];
        float4 vA = *(const float4*)&bufA[ndA][c * 4];
        float4 vB = *(const float4*)&bufA[ndB][c * 4];
        dA[0][0] += vA.x * w.x; dA[0][1] += vA.y * w.x; dA[0][2] += vA.z * w.x;
        dA[1][0] += vA.x * w.y; dA[1][1] += vA.y * w.y; dA[1][2] += vA.z * w.y;
        dA[2][0] += vA.x * w.z; dA[2][1] += vA.y * w.z; dA[2][2] += vA.z * w.z;
        dA[3][0] += vA.x * w.w; dA[3][1] += vA.y * w.w; dA[3][2] += vA.z * w.w;
        dB[0][0] += vB.x * w.x; dB[0][1] += vB.y * w.x; dB[0][2] += vB.z * w.x;
        dB[1][0] += vB.x * w.y; dB[1][1] += vB.y * w.y; dB[1][2] += vB.z * w.y;
        dB[2][0] += vB.x * w.z; dB[2][1] += vB.y * w.z; dB[2][2] += vB.z * w.z;
        dB[3][0] += vB.x * w.w; dB[3][1] += vB.y * w.w; dB[3][2] += vB.z * w.w;
    }

    float* out_vec = out + (size_t)N * 16;
#pragma unroll
    for (int half = 0; half < 2; half++) {
        bool act = half ? actB : actA;
        if (!act) continue;
        int n = half ? nB : nA;
        float (*ov)[3] = half ? ovB : ovA;
        float (*d)[3]  = half ? dB  : dA;
        float* osca    = half ? oscaB : oscaA;

        float res[12];
#pragma unroll
        for (int oo = 0; oo < 4; oo++) {
            float v0 = ov[oo][0], v1 = ov[oo][1], v2 = ov[oo][2];
            float d0 = d[oo][0], d1 = d[oo][1], d2 = d[oo][2];
            float dot = v0 * d0 + v1 * d1 + v2 * d2;
            float r0 = v0, r1 = v1, r2 = v2;
            if (dot < 0.0f) {
                float k = 0.8f * dot / (d0 * d0 + d1 * d1 + d2 * d2 + 1e-6f);
                r0 = v0 - k * d0; r1 = v1 - k * d1; r2 = v2 - k * d2;
            }
            res[oo * 3 + 0] = r0; res[oo * 3 + 1] = r1; res[oo * 3 + 2] = r2;
        }
        float4* dv = (float4*)(out_vec + (size_t)n * 48 + j * 12);
#pragma unroll
        for (int q = 0; q < 3; q++)
            dv[q] = make_float4(res[q * 4 + 0], res[q * 4 + 1],
                                res[q * 4 + 2], res[q * 4 + 3]);

        float s0 = osca[0], s1 = osca[1], s2 = osca[2], s3 = osca[3];
        s0 = (s0 >= 0.f) ? s0 : 0.01f * s0;
        s1 = (s1 >= 0.f) ? s1 : 0.01f * s1;
        s2 = (s2 >= 0.f) ? s2 : 0.01f * s2;
        s3 = (s3 >= 0.f) ? s3 : 0.01f * s3;
        ((float4*)(out + (size_t)n * 16 + o0))[0] = make_float4(s0, s1, s2, s3);
    }
}

// ---------------------------------------------------------------------------
extern "C" void kernel_launch(void* const* d_in, const int* in_sizes, int n_in,
                              void* d_out, int out_size) {
    const float* node_sca = (const float*)d_in[0];
    const float* node_vec = (const float*)d_in[1];
    const float* edge_sca = (const float*)d_in[2];
    const float* edge_vec = (const float*)d_in[3];
    const float* gds      = (const float*)d_in[4];
    const int*   ei       = (const int*)d_in[5];   // [2,E]; row 0 = src
    const float* W_nss  = (const float*)d_in[6];
    const float* b_nss  = (const float*)d_in[7];
    const float* W_ess  = (const float*)d_in[8];
    const float* b_ess  = (const float*)d_in[9];
    const float* W_nsv  = (const float*)d_in[10];
    const float* b_nsv  = (const float*)d_in[11];
    const float* W_esv  = (const float*)d_in[12];
    const float* b_esv  = (const float*)d_in[13];
    const float* W_nvv  = (const float*)d_in[14];
    const float* W_evv  = (const float*)d_in[15];
    const float* W_lv   = (const float*)d_in[16];
    const float* W_lv2  = (const float*)d_in[17];
    const float* W_ls   = (const float*)d_in[18];
    const float* W_gate = (const float*)d_in[19];
    const float* b_gate = (const float*)d_in[20];
    const float* W_dir  = (const float*)d_in[21];

    int N = in_sizes[0] / 4;
    int E = in_sizes[4];

    int eblocks = (E + EPB - 1) / EPB;
    edge_kernel<<<eblocks, EPB>>>(edge_sca, edge_vec, gds, ei, E);

    int nblocks = (N + NPB - 1) / NPB;
    node_kernel<<<nblocks, TPB>>>(node_sca, node_vec,
                                  W_nss, b_nss, W_ess, b_ess,
                                  W_nsv, b_nsv, W_esv, b_esv,
                                  W_nvv, W_evv, W_lv, W_lv2,
                                  W_ls, W_gate, b_gate, W_dir,
                                  (float*)d_out, N);
}

// round 16
// speedup vs baseline: 1.5832x; 1.0395x over previous
#include <cuda_runtime.h>
#include <math.h>

#define NMAX 100000
#define ACC_W 16   // [coeff, edge_sca*coeff (6), edge_vec*coeff (9)]
#define EPB 256    // edges per block in edge kernel

__device__ __align__(16) float g_acc[NMAX * ACC_W];   // zero-initialized at load

// ---------------------------------------------------------------------------
// Edge phase (R10 best-known): staged coalesced loads + red.v4.
// Triggers programmatic launch completion so the node kernel's preamble can
// overlap with this kernel's tail waves.
// ---------------------------------------------------------------------------
__device__ __forceinline__ void red_v4(float* p, float a, float b, float c, float d) {
    asm volatile("red.global.add.v4.f32 [%0], {%1,%2,%3,%4};"
                 :: "l"(p), "f"(a), "f"(b), "f"(c), "f"(d) : "memory");
}

__global__ void __launch_bounds__(EPB)
edge_kernel(const float* __restrict__ edge_sca,
            const float* __restrict__ edge_vec,
            const float* __restrict__ gds,
            const int*   __restrict__ src_idx,
            int E) {
    __shared__ float s_sca[EPB * 6];
    __shared__ float s_vec[EPB * 9];

    int blockStart = blockIdx.x * EPB;
    int tid = threadIdx.x;
    int nEdges = min(EPB, E - blockStart);

    if (nEdges == EPB) {
        const float4* g4s = (const float4*)(edge_sca + (size_t)blockStart * 6);
        float4* s4s = (float4*)s_sca;
#pragma unroll 2
        for (int i = tid; i < (EPB * 6) / 4; i += EPB)
            s4s[i] = g4s[i];
        const float4* g4v = (const float4*)(edge_vec + (size_t)blockStart * 9);
        float4* s4v = (float4*)s_vec;
#pragma unroll 3
        for (int i = tid; i < (EPB * 9) / 4; i += EPB)
            s4v[i] = g4v[i];
    } else {
        for (int i = tid; i < nEdges * 6; i += EPB)
            s_sca[i] = edge_sca[(size_t)blockStart * 6 + i];
        for (int i = tid; i < nEdges * 9; i += EPB)
            s_vec[i] = edge_vec[(size_t)blockStart * 9 + i];
    }
    __syncthreads();

    if (tid < nEdges) {
        int e = blockStart + tid;
        float dist = __ldg(gds + e);
        if (dist <= 10.0f && dist >= 0.0f) {
            float coeff = 0.5f * (__cosf(dist * 0.31415926535f) + 1.0f);
            int src = __ldg(src_idx + e);

            float es[6];
#pragma unroll
            for (int c = 0; c < 6; c++) es[c] = s_sca[tid * 6 + c] * coeff;
            float ev[9];
#pragma unroll
            for (int c = 0; c < 9; c++) ev[c] = s_vec[tid * 9 + c] * coeff;

            float* base = g_acc + (size_t)src * ACC_W;
            red_v4(base + 0,  coeff, es[0], es[1], es[2]);
            red_v4(base + 4,  es[3], es[4], es[5], ev[0]);
            red_v4(base + 8,  ev[1], ev[2], ev[3], ev[4]);
            red_v4(base + 12, ev[5], ev[6], ev[7], ev[8]);
        }
    }
    // allow the dependent node kernel to begin its (g_acc-independent) preamble
    cudaTriggerProgrammaticLaunchCompletion();
}

// ---------------------------------------------------------------------------
// Node phase: R10 structure (best known). Weight/node_vec staging runs BEFORE
// cudaGridDependencySynchronize(), overlapping the edge kernel tail.
// ---------------------------------------------------------------------------
#define O_NSS   0      // 4x16
#define O_BNSS  64     // 16
#define O_ESS   80     // 6x16
#define O_BESS  176    // 16
#define O_NSV   192    // 4x16
#define O_BNSV  256    // 16
#define O_ESV   272    // 6x16
#define O_BESV  368    // 16
#define O_NVV   384    // 3x16
#define O_EVV   432    // 3x16
#define O_LV    480    // 16x16
#define O_LV2   736    // 16x16
#define O_LS    992    // 32x16
#define O_GATE  1504   // 16x16
#define O_BGATE 1760   // 16
#define O_DIR   1776   // 16x16
#define SW_TOT  2032

#define NPB 64         // nodes per block
#define TPB 128        // threads (4 lanes x 32 node-pairs)
#define HALF_ND 32
#define BUF_W 68       // 64 payload + 4 pad floats

__global__ void __launch_bounds__(TPB)
node_kernel(const float* __restrict__ node_sca,
            const float* __restrict__ node_vec,
            const float* __restrict__ W_nss, const float* __restrict__ b_nss,
            const float* __restrict__ W_ess, const float* __restrict__ b_ess,
            const float* __restrict__ W_nsv, const float* __restrict__ b_nsv,
            const float* __restrict__ W_esv, const float* __restrict__ b_esv,
            const float* __restrict__ W_nvv, const float* __restrict__ W_evv,
            const float* __restrict__ W_lv,  const float* __restrict__ W_lv2,
            const float* __restrict__ W_ls,  const float* __restrict__ W_gate,
            const float* __restrict__ b_gate,const float* __restrict__ W_dir,
            float* __restrict__ out, int N) {
    __shared__ __align__(16) float sW[SW_TOT];
    __shared__ float s_nv[NPB * 9];
    __shared__ __align__(16) float bufA[NPB][BUF_W];  // aggr -> osca -> ovec
    __shared__ __align__(16) float bufB[NPB][BUF_W];  // v_inter + v_norm

    int tid = threadIdx.x;
    int ndA = tid >> 2;          // 0..31
    int ndB = ndA + HALF_ND;     // 32..63
    int j   = tid & 3;
    int o0  = j * 4;
    int blockStart = blockIdx.x * NPB;
    int nNodes = min(NPB, N - blockStart);
    int nA = blockStart + ndA;
    int nB = blockStart + ndB;
    bool actA = (ndA < nNodes);
    bool actB = (ndB < nNodes);

    {   // weights -> shared (independent of edge kernel)
        const float* srcs[16] = {W_nss, b_nss, W_ess, b_ess, W_nsv, b_nsv,
                                 W_esv, b_esv, W_nvv, W_evv, W_lv, W_lv2,
                                 W_ls, W_gate, b_gate, W_dir};
        const int offs[17] = {O_NSS, O_BNSS, O_ESS, O_BESS, O_NSV, O_BNSV,
                              O_ESV, O_BESV, O_NVV, O_EVV, O_LV, O_LV2,
                              O_LS, O_GATE, O_BGATE, O_DIR, SW_TOT};
        for (int a = 0; a < 16; a++) {
            int cnt = offs[a + 1] - offs[a];
            for (int i = tid; i < cnt; i += TPB)
                sW[offs[a] + i] = srcs[a][i];
        }
    }
    {   // node_vec -> shared (independent of edge kernel)
        for (int i = tid; i < nNodes * 9; i += TPB)
            s_nv[i] = node_vec[(size_t)blockStart * 9 + i];
    }
    __syncthreads();

    // wait until ALL edge-kernel reductions are complete & visible
    cudaGridDependencySynchronize();

    // ---- Phase 1 per node (inputs transient) ----
#pragma unroll
    for (int half = 0; half < 2; half++) {
        int nd = half ? ndB : ndA;
        int n  = half ? nB  : nA;
        bool act = half ? actB : actA;
        if (!act) continue;

        float4 ns4 = ((const float4*)node_sca)[n];
        float ns[4] = {ns4.x, ns4.y, ns4.z, ns4.w};
        float nv[9];
#pragma unroll
        for (int i = 0; i < 9; i++) nv[i] = s_nv[nd * 9 + i];
        float accv[16];
        {
            float4* a4 = (float4*)(g_acc + (size_t)n * ACC_W);
#pragma unroll
            for (int q = 0; q < 4; q++) {
                float4 v = a4[q];
                accv[q * 4 + 0] = v.x; accv[q * 4 + 1] = v.y;
                accv[q * 4 + 2] = v.z; accv[q * 4 + 3] = v.w;
            }
            a4[j] = make_float4(0.f, 0.f, 0.f, 0.f);   // reset quarter j
        }
        float Cs = accv[0];
        float* Es = accv + 1;
        float* Ev = accv + 7;

#pragma unroll
        for (int cc = 0; cc < 4; cc++) {
            int c = o0 + cc;
            float nss = sW[O_BNSS + c];
            float nsv = sW[O_BNSV + c];
#pragma unroll
            for (int k = 0; k < 4; k++) {
                nss += ns[k] * sW[O_NSS + k * 16 + c];
                nsv += ns[k] * sW[O_NSV + k * 16 + c];
            }
            float ess = sW[O_BESS + c] * Cs;
            float esv = sW[O_BESV + c] * Cs;
#pragma unroll
            for (int k = 0; k < 6; k++) {
                ess += Es[k] * sW[O_ESS + k * 16 + c];
                esv += Es[k] * sW[O_ESV + k * 16 + c];
            }
            float av[3];
#pragma unroll
            for (int i = 0; i < 3; i++) {
                float nvv = 0.f, evv = 0.f;
#pragma unroll
                for (int k = 0; k < 3; k++) {
                    nvv += nv[k * 3 + i] * sW[O_NVV + k * 16 + c];
                    evv += Ev[k * 3 + i] * sW[O_EVV + k * 16 + c];
                }
                av[i] = nvv * esv + nsv * evv;
            }
            *(float4*)&bufA[nd][c * 4] = make_float4(av[0], av[1], av[2], nss * ess);
        }
    }
    __syncwarp();

    // ---- Phase 2: lv + ls-scalar-half, both nodes share weight loads ----
    float viA[4][3], viB[4][3], oscaA[4], oscaB[4];
#pragma unroll
    for (int oo = 0; oo < 4; oo++) {
        viA[oo][0] = viA[oo][1] = viA[oo][2] = 0.f;
        viB[oo][0] = viB[oo][1] = viB[oo][2] = 0.f;
        oscaA[oo] = oscaB[oo] = 0.f;
    }
#pragma unroll
    for (int c = 0; c < 16; c++) {
        float4 wlv = *(const float4*)&sW[O_LV + c * 16 + o0];
        float4 wls = *(const float4*)&sW[O_LS + (c + 16) * 16 + o0];
        float4 a = *(const float4*)&bufA[ndA][c * 4];
        float4 b = *(const float4*)&bufA[ndB][c * 4];
        viA[0][0] += a.x * wlv.x; viA[0][1] += a.y * wlv.x; viA[0][2] += a.z * wlv.x;
        viA[1][0] += a.x * wlv.y; viA[1][1] += a.y * wlv.y; viA[1][2] += a.z * wlv.y;
        viA[2][0] += a.x * wlv.z; viA[2][1] += a.y * wlv.z; viA[2][2] += a.z * wlv.z;
        viA[3][0] += a.x * wlv.w; viA[3][1] += a.y * wlv.w; viA[3][2] += a.z * wlv.w;
        oscaA[0] += a.w * wls.x; oscaA[1] += a.w * wls.y;
        oscaA[2] += a.w * wls.z; oscaA[3] += a.w * wls.w;
        viB[0][0] += b.x * wlv.x; viB[0][1] += b.y * wlv.x; viB[0][2] += b.z * wlv.x;
        viB[1][0] += b.x * wlv.y; viB[1][1] += b.y * wlv.y; viB[1][2] += b.z * wlv.y;
        viB[2][0] += b.x * wlv.z; viB[2][1] += b.y * wlv.z; viB[2][2] += b.z * wlv.z;
        viB[3][0] += b.x * wlv.w; viB[3][1] += b.y * wlv.w; viB[3][2] += b.z * wlv.w;
        oscaB[0] += b.w * wls.x; oscaB[1] += b.w * wls.y;
        oscaB[2] += b.w * wls.z; oscaB[3] += b.w * wls.w;
    }
#pragma unroll
    for (int oo = 0; oo < 4; oo++) {
        float vnA = sqrtf(viA[oo][0] * viA[oo][0] + viA[oo][1] * viA[oo][1] +
                          viA[oo][2] * viA[oo][2]);
        *(float4*)&bufB[ndA][(o0 + oo) * 4] =
            make_float4(viA[oo][0], viA[oo][1], viA[oo][2], vnA);
        float vnB = sqrtf(viB[oo][0] * viB[oo][0] + viB[oo][1] * viB[oo][1] +
                          viB[oo][2] * viB[oo][2]);
        *(float4*)&bufB[ndB][(o0 + oo) * 4] =
            make_float4(viB[oo][0], viB[oo][1], viB[oo][2], vnB);
    }
    __syncwarp();

    // ---- Phase 3: osca v_norm-half; publish osca ----
#pragma unroll
    for (int c = 0; c < 16; c++) {
        float4 wls = *(const float4*)&sW[O_LS + c * 16 + o0];
        float vnA = bufB[ndA][c * 4 + 3];
        float vnB = bufB[ndB][c * 4 + 3];
        oscaA[0] += vnA * wls.x; oscaA[1] += vnA * wls.y;
        oscaA[2] += vnA * wls.z; oscaA[3] += vnA * wls.w;
        oscaB[0] += vnB * wls.x; oscaB[1] += vnB * wls.y;
        oscaB[2] += vnB * wls.z; oscaB[3] += vnB * wls.w;
    }
    *(float4*)&bufA[ndA][o0] = make_float4(oscaA[0], oscaA[1], oscaA[2], oscaA[3]);
    *(float4*)&bufA[ndB][o0] = make_float4(oscaB[0], oscaB[1], oscaB[2], oscaB[3]);
    __syncwarp();

    // ---- Phase 4: gate ----
    float gateA[4], gateB[4];
#pragma unroll
    for (int oo = 0; oo < 4; oo++) gateA[oo] = gateB[oo] = sW[O_BGATE + o0 + oo];
#pragma unroll
    for (int c4 = 0; c4 < 4; c4++) {
        float4 ocA = *(const float4*)&bufA[ndA][c4 * 4];
        float4 ocB = *(const float4*)&bufA[ndB][c4 * 4];
        float av[4] = {ocA.x, ocA.y, ocA.z, ocA.w};
        float bv[4] = {ocB.x, ocB.y, ocB.z, ocB.w};
#pragma unroll
        for (int q = 0; q < 4; q++) {
            float4 wg = *(const float4*)&sW[O_GATE + (c4 * 4 + q) * 16 + o0];
            gateA[0] += av[q] * wg.x; gateA[1] += av[q] * wg.y;
            gateA[2] += av[q] * wg.z; gateA[3] += av[q] * wg.w;
            gateB[0] += bv[q] * wg.x; gateB[1] += bv[q] * wg.y;
            gateB[2] += bv[q] * wg.z; gateB[3] += bv[q] * wg.w;
        }
    }
#pragma unroll
    for (int oo = 0; oo < 4; oo++) {
        gateA[oo] = 1.0f / (1.0f + __expf(-gateA[oo]));
        gateB[oo] = 1.0f / (1.0f + __expf(-gateB[oo]));
    }
    __syncwarp();   // osca reads done; bufA reusable for ovec

    // ---- Phase 5: lv2 -> ovec (gated); publish ----
    float ovA[4][3], ovB[4][3];
#pragma unroll
    for (int oo = 0; oo < 4; oo++) {
        ovA[oo][0] = ovA[oo][1] = ovA[oo][2] = 0.f;
        ovB[oo][0] = ovB[oo][1] = ovB[oo][2] = 0.f;
    }
#pragma unroll
    for (int c = 0; c < 16; c++) {
        float4 w = *(const float4*)&sW[O_LV2 + c * 16 + o0];
        float4 vA = *(const float4*)&bufB[ndA][c * 4];
        float4 vB = *(const float4*)&bufB[ndB][c * 4];
        ovA[0][0] += vA.x * w.x; ovA[0][1] += vA.y * w.x; ovA[0][2] += vA.z * w.x;
        ovA[1][0] += vA.x * w.y; ovA[1][1] += vA.y * w.y; ovA[1][2] += vA.z * w.y;
        ovA[2][0] += vA.x * w.z; ovA[2][1] += vA.y * w.z; ovA[2][2] += vA.z * w.z;
        ovA[3][0] += vA.x * w.w; ovA[3][1] += vA.y * w.w; ovA[3][2] += vA.z * w.w;
        ovB[0][0] += vB.x * w.x; ovB[0][1] += vB.y * w.x; ovB[0][2] += vB.z * w.x;
        ovB[1][0] += vB.x * w.y; ovB[1][1] += vB.y * w.y; ovB[1][2] += vB.z * w.y;
        ovB[2][0] += vB.x * w.z; ovB[2][1] += vB.y * w.z; ovB[2][2] += vB.z * w.z;
        ovB[3][0] += vB.x * w.w; ovB[3][1] += vB.y * w.w; ovB[3][2] += vB.z * w.w;
    }
#pragma unroll
    for (int oo = 0; oo < 4; oo++) {
        ovA[oo][0] *= gateA[oo]; ovA[oo][1] *= gateA[oo]; ovA[oo][2] *= gateA[oo];
        ovB[oo][0] *= gateB[oo]; ovB[oo][1] *= gateB[oo]; ovB[oo][2] *= gateB[oo];
        *(float4*)&bufA[ndA][(o0 + oo) * 4] =
            make_float4(ovA[oo][0], ovA[oo][1], ovA[oo][2], 0.f);
        *(float4*)&bufA[ndB][(o0 + oo) * 4] =
            make_float4(ovB[oo][0], ovB[oo][1], ovB[oo][2], 0.f);
    }
    __syncwarp();

    // ---- Phase 6: direction + VNLeakyReLU + writes ----
    float dA[4][3], dB[4][3];
#pragma unroll
    for (int oo = 0; oo < 4; oo++) {
        dA[oo][0] = dA[oo][1] = dA[oo][2] = 0.f;
        dB[oo][0] = dB[oo][1] = dB[oo][2] = 0.f;
    }
#pragma unroll
    for (int c = 0; c < 16; c++) {
        float4 w = *(const float4*)&sW[O_DIR + c * 16 + o0];
        float4 vA = *(const float4*)&bufA[ndA][c * 4];
        float4 vB = *(const float4*)&bufA[ndB][c * 4];
        dA[0][0] += vA.x * w.x; dA[0][1] += vA.y * w.x; dA[0][2] += vA.z * w.x;
        dA[1][0] += vA.x * w.y; dA[1][1] += vA.y * w.y; dA[1][2] += vA.z * w.y;
        dA[2][0] += vA.x * w.z; dA[2][1] += vA.y * w.z; dA[2][2] += vA.z * w.z;
        dA[3][0] += vA.x * w.w; dA[3][1] += vA.y * w.w; dA[3][2] += vA.z * w.w;
        dB[0][0] += vB.x * w.x; dB[0][1] += vB.y * w.x; dB[0][2] += vB.z * w.x;
        dB[1][0] += vB.x * w.y; dB[1][1] += vB.y * w.y; dB[1][2] += vB.z * w.y;
        dB[2][0] += vB.x * w.z; dB[2][1] += vB.y * w.z; dB[2][2] += vB.z * w.z;
        dB[3][0] += vB.x * w.w; dB[3][1] += vB.y * w.w; dB[3][2] += vB.z * w.w;
    }

    float* out_vec = out + (size_t)N * 16;
#pragma unroll
    for (int half = 0; half < 2; half++) {
        bool act = half ? actB : actA;
        if (!act) continue;
        int n = half ? nB : nA;
        float (*ov)[3] = half ? ovB : ovA;
        float (*d)[3]  = half ? dB  : dA;
        float* osca    = half ? oscaB : oscaA;

        float res[12];
#pragma unroll
        for (int oo = 0; oo < 4; oo++) {
            float v0 = ov[oo][0], v1 = ov[oo][1], v2 = ov[oo][2];
            float d0 = d[oo][0], d1 = d[oo][1], d2 = d[oo][2];
            float dot = v0 * d0 + v1 * d1 + v2 * d2;
            float r0 = v0, r1 = v1, r2 = v2;
            if (dot < 0.0f) {
                float k = 0.8f * dot / (d0 * d0 + d1 * d1 + d2 * d2 + 1e-6f);
                r0 = v0 - k * d0; r1 = v1 - k * d1; r2 = v2 - k * d2;
            }
            res[oo * 3 + 0] = r0; res[oo * 3 + 1] = r1; res[oo * 3 + 2] = r2;
        }
        float4* dv = (float4*)(out_vec + (size_t)n * 48 + j * 12);
#pragma unroll
        for (int q = 0; q < 3; q++)
            dv[q] = make_float4(res[q * 4 + 0], res[q * 4 + 1],
                                res[q * 4 + 2], res[q * 4 + 3]);

        float s0 = osca[0], s1 = osca[1], s2 = osca[2], s3 = osca[3];
        s0 = (s0 >= 0.f) ? s0 : 0.01f * s0;
        s1 = (s1 >= 0.f) ? s1 : 0.01f * s1;
        s2 = (s2 >= 0.f) ? s2 : 0.01f * s2;
        s3 = (s3 >= 0.f) ? s3 : 0.01f * s3;
        ((float4*)(out + (size_t)n * 16 + o0))[0] = make_float4(s0, s1, s2, s3);
    }
}

// ---------------------------------------------------------------------------
extern "C" void kernel_launch(void* const* d_in, const int* in_sizes, int n_in,
                              void* d_out, int out_size) {
    const float* node_sca = (const float*)d_in[0];
    const float* node_vec = (const float*)d_in[1];
    const float* edge_sca = (const float*)d_in[2];
    const float* edge_vec = (const float*)d_in[3];
    const float* gds      = (const float*)d_in[4];
    const int*   ei       = (const int*)d_in[5];   // [2,E]; row 0 = src
    const float* W_nss  = (const float*)d_in[6];
    const float* b_nss  = (const float*)d_in[7];
    const float* W_ess  = (const float*)d_in[8];
    const float* b_ess  = (const float*)d_in[9];
    const float* W_nsv  = (const float*)d_in[10];
    const float* b_nsv  = (const float*)d_in[11];
    const float* W_esv  = (const float*)d_in[12];
    const float* b_esv  = (const float*)d_in[13];
    const float* W_nvv  = (const float*)d_in[14];
    const float* W_evv  = (const float*)d_in[15];
    const float* W_lv   = (const float*)d_in[16];
    const float* W_lv2  = (const float*)d_in[17];
    const float* W_ls   = (const float*)d_in[18];
    const float* W_gate = (const float*)d_in[19];
    const float* b_gate = (const float*)d_in[20];
    const float* W_dir  = (const float*)d_in[21];

    int N = in_sizes[0] / 4;
    int E = in_sizes[4];

    int eblocks = (E + EPB - 1) / EPB;
    edge_kernel<<<eblocks, EPB>>>(edge_sca, edge_vec, gds, ei, E);

    int nblocks = (N + NPB - 1) / NPB;

    // Programmatic dependent launch: node kernel may begin its preamble
    // (weight staging) while the edge kernel tail is still running; it
    // synchronizes on edge completion via cudaGridDependencySynchronize().
    cudaLaunchConfig_t cfg = {};
    cfg.gridDim = dim3(nblocks, 1, 1);
    cfg.blockDim = dim3(TPB, 1, 1);
    cfg.dynamicSmemBytes = 0;
    cfg.stream = 0;
    cudaLaunchAttribute attrs[1];
    attrs[0].id = cudaLaunchAttributeProgrammaticStreamSerialization;
    attrs[0].val.programmaticStreamSerializationAllowed = 1;
    cfg.attrs = attrs;
    cfg.numAttrs = 1;

    cudaLaunchKernelEx(&cfg, node_kernel,
                       node_sca, node_vec,
                       W_nss, b_nss, W_ess, b_ess,
                       W_nsv, b_nsv, W_esv, b_esv,
                       W_nvv, W_evv, W_lv, W_lv2,
                       W_ls, W_gate, b_gate, W_dir,
                       (float*)d_out, N);
}

// round 17
// speedup vs baseline: 1.6350x; 1.0328x over previous
#include <cuda_runtime.h>
#include <math.h>

#define NMAX 100000
#define ACC_W 16   // [coeff, edge_sca*coeff (6), edge_vec*coeff (9)]
#define EPB 256    // edges per block in edge kernel

__device__ __align__(16) float g_acc[NMAX * ACC_W];   // zero-initialized at load

// ---------------------------------------------------------------------------
// Edge phase (R10 best-known): staged coalesced loads + red.v4.
// Programmatic-launch trigger at the TOP of the kernel: dependent node grid
// begins launching (and running its g_acc-independent preamble) while this
// grid is still executing; node kernel's cudaGridDependencySynchronize()
// provides the correctness barrier.
// ---------------------------------------------------------------------------
__device__ __forceinline__ void red_v4(float* p, float a, float b, float c, float d) {
    asm volatile("red.global.add.v4.f32 [%0], {%1,%2,%3,%4};"
                 :: "l"(p), "f"(a), "f"(b), "f"(c), "f"(d) : "memory");
}

__global__ void __launch_bounds__(EPB)
edge_kernel(const float* __restrict__ edge_sca,
            const float* __restrict__ edge_vec,
            const float* __restrict__ gds,
            const int*   __restrict__ src_idx,
            int E) {
    cudaTriggerProgrammaticLaunchCompletion();   // earliest possible trigger

    __shared__ float s_sca[EPB * 6];
    __shared__ float s_vec[EPB * 9];

    int blockStart = blockIdx.x * EPB;
    int tid = threadIdx.x;
    int nEdges = min(EPB, E - blockStart);

    if (nEdges == EPB) {
        const float4* g4s = (const float4*)(edge_sca + (size_t)blockStart * 6);
        float4* s4s = (float4*)s_sca;
#pragma unroll 2
        for (int i = tid; i < (EPB * 6) / 4; i += EPB)
            s4s[i] = g4s[i];
        const float4* g4v = (const float4*)(edge_vec + (size_t)blockStart * 9);
        float4* s4v = (float4*)s_vec;
#pragma unroll 3
        for (int i = tid; i < (EPB * 9) / 4; i += EPB)
            s4v[i] = g4v[i];
    } else {
        for (int i = tid; i < nEdges * 6; i += EPB)
            s_sca[i] = edge_sca[(size_t)blockStart * 6 + i];
        for (int i = tid; i < nEdges * 9; i += EPB)
            s_vec[i] = edge_vec[(size_t)blockStart * 9 + i];
    }
    __syncthreads();

    if (tid >= nEdges) return;
    int e = blockStart + tid;

    float dist = __ldg(gds + e);
    if (dist > 10.0f || dist < 0.0f) return;     // coeff == 0 -> no contribution
    float coeff = 0.5f * (__cosf(dist * 0.31415926535f) + 1.0f);

    int src = __ldg(src_idx + e);

    float es[6];
#pragma unroll
    for (int c = 0; c < 6; c++) es[c] = s_sca[tid * 6 + c] * coeff;
    float ev[9];
#pragma unroll
    for (int c = 0; c < 9; c++) ev[c] = s_vec[tid * 9 + c] * coeff;

    float* base = g_acc + (size_t)src * ACC_W;
    red_v4(base + 0,  coeff, es[0], es[1], es[2]);
    red_v4(base + 4,  es[3], es[4], es[5], ev[0]);
    red_v4(base + 8,  ev[1], ev[2], ev[3], ev[4]);
    red_v4(base + 12, ev[5], ev[6], ev[7], ev[8]);
}

// ---------------------------------------------------------------------------
// Node phase: R10 structure (best known). Weight/node_vec staging runs BEFORE
// cudaGridDependencySynchronize(), overlapping the edge kernel execution.
// ---------------------------------------------------------------------------
#define O_NSS   0      // 4x16
#define O_BNSS  64     // 16
#define O_ESS   80     // 6x16
#define O_BESS  176    // 16
#define O_NSV   192    // 4x16
#define O_BNSV  256    // 16
#define O_ESV   272    // 6x16
#define O_BESV  368    // 16
#define O_NVV   384    // 3x16
#define O_EVV   432    // 3x16
#define O_LV    480    // 16x16
#define O_LV2   736    // 16x16
#define O_LS    992    // 32x16
#define O_GATE  1504   // 16x16
#define O_BGATE 1760   // 16
#define O_DIR   1776   // 16x16
#define SW_TOT  2032

#define NPB 64         // nodes per block
#define TPB 128        // threads (4 lanes x 32 node-pairs)
#define HALF_ND 32
#define BUF_W 68       // 64 payload + 4 pad floats

__global__ void __launch_bounds__(TPB)
node_kernel(const float* __restrict__ node_sca,
            const float* __restrict__ node_vec,
            const float* __restrict__ W_nss, const float* __restrict__ b_nss,
            const float* __restrict__ W_ess, const float* __restrict__ b_ess,
            const float* __restrict__ W_nsv, const float* __restrict__ b_nsv,
            const float* __restrict__ W_esv, const float* __restrict__ b_esv,
            const float* __restrict__ W_nvv, const float* __restrict__ W_evv,
            const float* __restrict__ W_lv,  const float* __restrict__ W_lv2,
            const float* __restrict__ W_ls,  const float* __restrict__ W_gate,
            const float* __restrict__ b_gate,const float* __restrict__ W_dir,
            float* __restrict__ out, int N) {
    __shared__ __align__(16) float sW[SW_TOT];
    __shared__ float s_nv[NPB * 9];
    __shared__ __align__(16) float bufA[NPB][BUF_W];  // aggr -> osca -> ovec
    __shared__ __align__(16) float bufB[NPB][BUF_W];  // v_inter + v_norm

    int tid = threadIdx.x;
    int ndA = tid >> 2;          // 0..31
    int ndB = ndA + HALF_ND;     // 32..63
    int j   = tid & 3;
    int o0  = j * 4;
    int blockStart = blockIdx.x * NPB;
    int nNodes = min(NPB, N - blockStart);
    int nA = blockStart + ndA;
    int nB = blockStart + ndB;
    bool actA = (ndA < nNodes);
    bool actB = (ndB < nNodes);

    {   // weights -> shared (independent of edge kernel)
        const float* srcs[16] = {W_nss, b_nss, W_ess, b_ess, W_nsv, b_nsv,
                                 W_esv, b_esv, W_nvv, W_evv, W_lv, W_lv2,
                                 W_ls, W_gate, b_gate, W_dir};
        const int offs[17] = {O_NSS, O_BNSS, O_ESS, O_BESS, O_NSV, O_BNSV,
                              O_ESV, O_BESV, O_NVV, O_EVV, O_LV, O_LV2,
                              O_LS, O_GATE, O_BGATE, O_DIR, SW_TOT};
        for (int a = 0; a < 16; a++) {
            int cnt = offs[a + 1] - offs[a];
            for (int i = tid; i < cnt; i += TPB)
                sW[offs[a] + i] = srcs[a][i];
        }
    }
    {   // node_vec -> shared (independent of edge kernel)
        for (int i = tid; i < nNodes * 9; i += TPB)
            s_nv[i] = node_vec[(size_t)blockStart * 9 + i];
    }
    __syncthreads();

    // wait until ALL edge-kernel reductions are complete & visible
    cudaGridDependencySynchronize();

    // ---- Phase 1 per node (inputs transient) ----
#pragma unroll
    for (int half = 0; half < 2; half++) {
        int nd = half ? ndB : ndA;
        int n  = half ? nB  : nA;
        bool act = half ? actB : actA;
        if (!act) continue;

        float4 ns4 = ((const float4*)node_sca)[n];
        float ns[4] = {ns4.x, ns4.y, ns4.z, ns4.w};
        float nv[9];
#pragma unroll
        for (int i = 0; i < 9; i++) nv[i] = s_nv[nd * 9 + i];
        float accv[16];
        {
            float4* a4 = (float4*)(g_acc + (size_t)n * ACC_W);
#pragma unroll
            for (int q = 0; q < 4; q++) {
                float4 v = a4[q];
                accv[q * 4 + 0] = v.x; accv[q * 4 + 1] = v.y;
                accv[q * 4 + 2] = v.z; accv[q * 4 + 3] = v.w;
            }
            a4[j] = make_float4(0.f, 0.f, 0.f, 0.f);   // reset quarter j
        }
        float Cs = accv[0];
        float* Es = accv + 1;
        float* Ev = accv + 7;

#pragma unroll
        for (int cc = 0; cc < 4; cc++) {
            int c = o0 + cc;
            float nss = sW[O_BNSS + c];
            float nsv = sW[O_BNSV + c];
#pragma unroll
            for (int k = 0; k < 4; k++) {
                nss += ns[k] * sW[O_NSS + k * 16 + c];
                nsv += ns[k] * sW[O_NSV + k * 16 + c];
            }
            float ess = sW[O_BESS + c] * Cs;
            float esv = sW[O_BESV + c] * Cs;
#pragma unroll
            for (int k = 0; k < 6; k++) {
                ess += Es[k] * sW[O_ESS + k * 16 + c];
                esv += Es[k] * sW[O_ESV + k * 16 + c];
            }
            float av[3];
#pragma unroll
            for (int i = 0; i < 3; i++) {
                float nvv = 0.f, evv = 0.f;
#pragma unroll
                for (int k = 0; k < 3; k++) {
                    nvv += nv[k * 3 + i] * sW[O_NVV + k * 16 + c];
                    evv += Ev[k * 3 + i] * sW[O_EVV + k * 16 + c];
                }
                av[i] = nvv * esv + nsv * evv;
            }
            *(float4*)&bufA[nd][c * 4] = make_float4(av[0], av[1], av[2], nss * ess);
        }
    }
    __syncwarp();

    // ---- Phase 2: lv + ls-scalar-half, both nodes share weight loads ----
    float viA[4][3], viB[4][3], oscaA[4], oscaB[4];
#pragma unroll
    for (int oo = 0; oo < 4; oo++) {
        viA[oo][0] = viA[oo][1] = viA[oo][2] = 0.f;
        viB[oo][0] = viB[oo][1] = viB[oo][2] = 0.f;
        oscaA[oo] = oscaB[oo] = 0.f;
    }
#pragma unroll
    for (int c = 0; c < 16; c++) {
        float4 wlv = *(const float4*)&sW[O_LV + c * 16 + o0];
        float4 wls = *(const float4*)&sW[O_LS + (c + 16) * 16 + o0];
        float4 a = *(const float4*)&bufA[ndA][c * 4];
        float4 b = *(const float4*)&bufA[ndB][c * 4];
        viA[0][0] += a.x * wlv.x; viA[0][1] += a.y * wlv.x; viA[0][2] += a.z * wlv.x;
        viA[1][0] += a.x * wlv.y; viA[1][1] += a.y * wlv.y; viA[1][2] += a.z * wlv.y;
        viA[2][0] += a.x * wlv.z; viA[2][1] += a.y * wlv.z; viA[2][2] += a.z * wlv.z;
        viA[3][0] += a.x * wlv.w; viA[3][1] += a.y * wlv.w; viA[3][2] += a.z * wlv.w;
        oscaA[0] += a.w * wls.x; oscaA[1] += a.w * wls.y;
        oscaA[2] += a.w * wls.z; oscaA[3] += a.w * wls.w;
        viB[0][0] += b.x * wlv.x; viB[0][1] += b.y * wlv.x; viB[0][2] += b.z * wlv.x;
        viB[1][0] += b.x * wlv.y; viB[1][1] += b.y * wlv.y; viB[1][2] += b.z * wlv.y;
        viB[2][0] += b.x * wlv.z; viB[2][1] += b.y * wlv.z; viB[2][2] += b.z * wlv.z;
        viB[3][0] += b.x * wlv.w; viB[3][1] += b.y * wlv.w; viB[3][2] += b.z * wlv.w;
        oscaB[0] += b.w * wls.x; oscaB[1] += b.w * wls.y;
        oscaB[2] += b.w * wls.z; oscaB[3] += b.w * wls.w;
    }
#pragma unroll
    for (int oo = 0; oo < 4; oo++) {
        float vnA = sqrtf(viA[oo][0] * viA[oo][0] + viA[oo][1] * viA[oo][1] +
                          viA[oo][2] * viA[oo][2]);
        *(float4*)&bufB[ndA][(o0 + oo) * 4] =
            make_float4(viA[oo][0], viA[oo][1], viA[oo][2], vnA);
        float vnB = sqrtf(viB[oo][0] * viB[oo][0] + viB[oo][1] * viB[oo][1] +
                          viB[oo][2] * viB[oo][2]);
        *(float4*)&bufB[ndB][(o0 + oo) * 4] =
            make_float4(viB[oo][0], viB[oo][1], viB[oo][2], vnB);
    }
    __syncwarp();

    // ---- Phase 3: osca v_norm-half; publish osca ----
#pragma unroll
    for (int c = 0; c < 16; c++) {
        float4 wls = *(const float4*)&sW[O_LS + c * 16 + o0];
        float vnA = bufB[ndA][c * 4 + 3];
        float vnB = bufB[ndB][c * 4 + 3];
        oscaA[0] += vnA * wls.x; oscaA[1] += vnA * wls.y;
        oscaA[2] += vnA * wls.z; oscaA[3] += vnA * wls.w;
        oscaB[0] += vnB * wls.x; oscaB[1] += vnB * wls.y;
        oscaB[2] += vnB * wls.z; oscaB[3] += vnB * wls.w;
    }
    *(float4*)&bufA[ndA][o0] = make_float4(oscaA[0], oscaA[1], oscaA[2], oscaA[3]);
    *(float4*)&bufA[ndB][o0] = make_float4(oscaB[0], oscaB[1], oscaB[2], oscaB[3]);
    __syncwarp();

    // ---- Phase 4: gate ----
    float gateA[4], gateB[4];
#pragma unroll
    for (int oo = 0; oo < 4; oo++) gateA[oo] = gateB[oo] = sW[O_BGATE + o0 + oo];
#pragma unroll
    for (int c4 = 0; c4 < 4; c4++) {
        float4 ocA = *(const float4*)&bufA[ndA][c4 * 4];
        float4 ocB = *(const float4*)&bufA[ndB][c4 * 4];
        float av[4] = {ocA.x, ocA.y, ocA.z, ocA.w};
        float bv[4] = {ocB.x, ocB.y, ocB.z, ocB.w};
#pragma unroll
        for (int q = 0; q < 4; q++) {
            float4 wg = *(const float4*)&sW[O_GATE + (c4 * 4 + q) * 16 + o0];
            gateA[0] += av[q] * wg.x; gateA[1] += av[q] * wg.y;
            gateA[2] += av[q] * wg.z; gateA[3] += av[q] * wg.w;
            gateB[0] += bv[q] * wg.x; gateB[1] += bv[q] * wg.y;
            gateB[2] += bv[q] * wg.z; gateB[3] += bv[q] * wg.w;
        }
    }
#pragma unroll
    for (int oo = 0; oo < 4; oo++) {
        gateA[oo] = 1.0f / (1.0f + __expf(-gateA[oo]));
        gateB[oo] = 1.0f / (1.0f + __expf(-gateB[oo]));
    }
    __syncwarp();   // osca reads done; bufA reusable for ovec

    // ---- Phase 5: lv2 -> ovec (gated); publish ----
    float ovA[4][3], ovB[4][3];
#pragma unroll
    for (int oo = 0; oo < 4; oo++) {
        ovA[oo][0] = ovA[oo][1] = ovA[oo][2] = 0.f;
        ovB[oo][0] = ovB[oo][1] = ovB[oo][2] = 0.f;
    }
#pragma unroll
    for (int c = 0; c < 16; c++) {
        float4 w = *(const float4*)&sW[O_LV2 + c * 16 + o0];
        float4 vA = *(const float4*)&bufB[ndA][c * 4];
        float4 vB = *(const float4*)&bufB[ndB][c * 4];
        ovA[0][0] += vA.x * w.x; ovA[0][1] += vA.y * w.x; ovA[0][2] += vA.z * w.x;
        ovA[1][0] += vA.x * w.y; ovA[1][1] += vA.y * w.y; ovA[1][2] += vA.z * w.y;
        ovA[2][0] += vA.x * w.z; ovA[2][1] += vA.y * w.z; ovA[2][2] += vA.z * w.z;
        ovA[3][0] += vA.x * w.w; ovA[3][1] += vA.y * w.w; ovA[3][2] += vA.z * w.w;
        ovB[0][0] += vB.x * w.x; ovB[0][1] += vB.y * w.x; ovB[0][2] += vB.z * w.x;
        ovB[1][0] += vB.x * w.y; ovB[1][1] += vB.y * w.y; ovB[1][2] += vB.z * w.y;
        ovB[2][0] += vB.x * w.z; ovB[2][1] += vB.y * w.z; ovB[2][2] += vB.z * w.z;
        ovB[3][0] += vB.x * w.w; ovB[3][1] += vB.y * w.w; ovB[3][2] += vB.z * w.w;
    }
#pragma unroll
    for (int oo = 0; oo < 4; oo++) {
        ovA[oo][0] *= gateA[oo]; ovA[oo][1] *= gateA[oo]; ovA[oo][2] *= gateA[oo];
        ovB[oo][0] *= gateB[oo]; ovB[oo][1] *= gateB[oo]; ovB[oo][2] *= gateB[oo];
        *(float4*)&bufA[ndA][(o0 + oo) * 4] =
            make_float4(ovA[oo][0], ovA[oo][1], ovA[oo][2], 0.f);
        *(float4*)&bufA[ndB][(o0 + oo) * 4] =
            make_float4(ovB[oo][0], ovB[oo][1], ovB[oo][2], 0.f);
    }
    __syncwarp();

    // ---- Phase 6: direction + VNLeakyReLU + writes ----
    float dA[4][3], dB[4][3];
#pragma unroll
    for (int oo = 0; oo < 4; oo++) {
        dA[oo][0] = dA[oo][1] = dA[oo][2] = 0.f;
        dB[oo][0] = dB[oo][1] = dB[oo][2] = 0.f;
    }
#pragma unroll
    for (int c = 0; c < 16; c++) {
        float4 w = *(const float4*)&sW[O_DIR + c * 16 + o0];
        float4 vA = *(const float4*)&bufA[ndA][c * 4];
        float4 vB = *(const float4*)&bufA[ndB][c * 4];
        dA[0][0] += vA.x * w.x; dA[0][1] += vA.y * w.x; dA[0][2] += vA.z * w.x;
        dA[1][0] += vA.x * w.y; dA[1][1] += vA.y * w.y; dA[1][2] += vA.z * w.y;
        dA[2][0] += vA.x * w.z; dA[2][1] += vA.y * w.z; dA[2][2] += vA.z * w.z;
        dA[3][0] += vA.x * w.w; dA[3][1] += vA.y * w.w; dA[3][2] += vA.z * w.w;
        dB[0][0] += vB.x * w.x; dB[0][1] += vB.y * w.x; dB[0][2] += vB.z * w.x;
        dB[1][0] += vB.x * w.y; dB[1][1] += vB.y * w.y; dB[1][2] += vB.z * w.y;
        dB[2][0] += vB.x * w.z; dB[2][1] += vB.y * w.z; dB[2][2] += vB.z * w.z;
        dB[3][0] += vB.x * w.w; dB[3][1] += vB.y * w.w; dB[3][2] += vB.z * w.w;
    }

    float* out_vec = out + (size_t)N * 16;
#pragma unroll
    for (int half = 0; half < 2; half++) {
        bool act = half ? actB : actA;
        if (!act) continue;
        int n = half ? nB : nA;
        float (*ov)[3] = half ? ovB : ovA;
        float (*d)[3]  = half ? dB  : dA;
        float* osca    = half ? oscaB : oscaA;

        float res[12];
#pragma unroll
        for (int oo = 0; oo < 4; oo++) {
            float v0 = ov[oo][0], v1 = ov[oo][1], v2 = ov[oo][2];
            float d0 = d[oo][0], d1 = d[oo][1], d2 = d[oo][2];
            float dot = v0 * d0 + v1 * d1 + v2 * d2;
            float r0 = v0, r1 = v1, r2 = v2;
            if (dot < 0.0f) {
                float k = 0.8f * dot / (d0 * d0 + d1 * d1 + d2 * d2 + 1e-6f);
                r0 = v0 - k * d0; r1 = v1 - k * d1; r2 = v2 - k * d2;
            }
            res[oo * 3 + 0] = r0; res[oo * 3 + 1] = r1; res[oo * 3 + 2] = r2;
        }
        float4* dv = (float4*)(out_vec + (size_t)n * 48 + j * 12);
#pragma unroll
        for (int q = 0; q < 3; q++)
            dv[q] = make_float4(res[q * 4 + 0], res[q * 4 + 1],
                                res[q * 4 + 2], res[q * 4 + 3]);

        float s0 = osca[0], s1 = osca[1], s2 = osca[2], s3 = osca[3];
        s0 = (s0 >= 0.f) ? s0 : 0.01f * s0;
        s1 = (s1 >= 0.f) ? s1 : 0.01f * s1;
        s2 = (s2 >= 0.f) ? s2 : 0.01f * s2;
        s3 = (s3 >= 0.f) ? s3 : 0.01f * s3;
        ((float4*)(out + (size_t)n * 16 + o0))[0] = make_float4(s0, s1, s2, s3);
    }
}

// ---------------------------------------------------------------------------
extern "C" void kernel_launch(void* const* d_in, const int* in_sizes, int n_in,
                              void* d_out, int out_size) {
    const float* node_sca = (const float*)d_in[0];
    const float* node_vec = (const float*)d_in[1];
    const float* edge_sca = (const float*)d_in[2];
    const float* edge_vec = (const float*)d_in[3];
    const float* gds      = (const float*)d_in[4];
    const int*   ei       = (const int*)d_in[5];   // [2,E]; row 0 = src
    const float* W_nss  = (const float*)d_in[6];
    const float* b_nss  = (const float*)d_in[7];
    const float* W_ess  = (const float*)d_in[8];
    const float* b_ess  = (const float*)d_in[9];
    const float* W_nsv  = (const float*)d_in[10];
    const float* b_nsv  = (const float*)d_in[11];
    const float* W_esv  = (const float*)d_in[12];
    const float* b_esv  = (const float*)d_in[13];
    const float* W_nvv  = (const float*)d_in[14];
    const float* W_evv  = (const float*)d_in[15];
    const float* W_lv   = (const float*)d_in[16];
    const float* W_lv2  = (const float*)d_in[17];
    const float* W_ls   = (const float*)d_in[18];
    const float* W_gate = (const float*)d_in[19];
    const float* b_gate = (const float*)d_in[20];
    const float* W_dir  = (const float*)d_in[21];

    int N = in_sizes[0] / 4;
    int E = in_sizes[4];

    int eblocks = (E + EPB - 1) / EPB;
    edge_kernel<<<eblocks, EPB>>>(edge_sca, edge_vec, gds, ei, E);

    int nblocks = (N + NPB - 1) / NPB;

    // Programmatic dependent launch: node kernel begins its preamble
    // (weight staging) while the edge kernel is still running; it
    // synchronizes on edge completion via cudaGridDependencySynchronize().
    cudaLaunchConfig_t cfg = {};
    cfg.gridDim = dim3(nblocks, 1, 1);
    cfg.blockDim = dim3(TPB, 1, 1);
    cfg.dynamicSmemBytes = 0;
    cfg.stream = 0;
    cudaLaunchAttribute attrs[1];
    attrs[0].id = cudaLaunchAttributeProgrammaticStreamSerialization;
    attrs[0].val.programmaticStreamSerializationAllowed = 1;
    cfg.attrs = attrs;
    cfg.numAttrs = 1;

    cudaLaunchKernelEx(&cfg, node_kernel,
                       node_sca, node_vec,
                       W_nss, b_nss, W_ess, b_ess,
                       W_nsv, b_nsv, W_esv, b_esv,
                       W_nvv, W_evv, W_lv, W_lv2,
                       W_ls, W_gate, b_gate, W_dir,
                       (float*)d_out, N);
}